// round 1
// baseline (speedup 1.0000x reference)
#include <cuda_runtime.h>
#include <cstdint>

// Problem constants
#define Bdim 8
#define Ndim 512
#define Sdim 4096
#define Hdim 1024

// Tiling
#define BM 128
#define BN 128
#define BK 16
#define APAD 4
#define NTHREADS 256

using u64 = unsigned long long;

// Packed f32x2 FMA (Blackwell FFMA2) — only reachable via PTX.
__device__ __forceinline__ u64 ffma2(u64 a, u64 b, u64 c) {
    u64 d;
    asm("fma.rn.f32x2 %0, %1, %2, %3;" : "=l"(d) : "l"(a), "l"(b), "l"(c));
    return d;
}
__device__ __forceinline__ u64 pack2_dup(float x) {
    u64 d;
    asm("mov.b64 %0, {%1, %1};" : "=l"(d) : "f"(x));
    return d;
}
__device__ __forceinline__ u64 pack2(float lo, float hi) {
    u64 d;
    asm("mov.b64 %0, {%1, %2};" : "=l"(d) : "f"(lo), "f"(hi));
    return d;
}
__device__ __forceinline__ void unpack2(u64 v, float& lo, float& hi) {
    asm("mov.b64 {%0, %1}, %2;" : "=f"(lo), "=f"(hi) : "l"(v));
}

__global__ void __launch_bounds__(NTHREADS, 2)
mean_pool_gemm(const float* __restrict__ doc,   // [B, S, H]
               const float* __restrict__ map,   // [B, N, S]
               const float* __restrict__ lens,  // [B, N]
               float* __restrict__ out)         // [B, N, H]
{
    __shared__ float As[2][BK][BM + APAD];  // A^T tile: [k][m]
    __shared__ float Bs[2][BK][BN];         // B tile:   [k][h]

    const int b  = blockIdx.z;
    const int m0 = blockIdx.y * BM;   // n offset
    const int h0 = blockIdx.x * BN;   // h offset

    const float* Aptr = map + (size_t)b * Ndim * Sdim + (size_t)m0 * Sdim;  // [BM, S]
    const float* Bptr = doc + (size_t)b * Sdim * Hdim + h0;                 // [S, BN]

    const int tid = threadIdx.x;
    const int tx  = tid & 15;   // h direction (8 cols each)
    const int ty  = tid >> 4;   // n direction (8 rows each)

    u64 acc[8][4];
    #pragma unroll
    for (int i = 0; i < 8; i++)
        #pragma unroll
        for (int j = 0; j < 4; j++)
            acc[i][j] = 0ull;

    auto load_tile = [&](int st, int k0) {
        #pragma unroll
        for (int i = 0; i < 2; i++) {
            const int l = tid + i * NTHREADS;   // 0..511
            // A: 128 rows x 16 cols = 512 float4 (4 per row)
            {
                const int row = l >> 2;
                const int c4  = l & 3;
                float4 v = *reinterpret_cast<const float4*>(
                    Aptr + (size_t)row * Sdim + k0 + c4 * 4);
                As[st][c4 * 4 + 0][row] = v.x;
                As[st][c4 * 4 + 1][row] = v.y;
                As[st][c4 * 4 + 2][row] = v.z;
                As[st][c4 * 4 + 3][row] = v.w;
            }
            // B: 16 rows x 128 cols = 512 float4 (32 per row)
            {
                const int row = l >> 5;
                const int c4  = l & 31;
                float4 v = *reinterpret_cast<const float4*>(
                    Bptr + (size_t)(k0 + row) * Hdim + c4 * 4);
                *reinterpret_cast<float4*>(&Bs[st][row][c4 * 4]) = v;
            }
        }
    };

    load_tile(0, 0);
    __syncthreads();

    const int NK = Sdim / BK;   // 256
    for (int kt = 0; kt < NK; kt++) {
        const int cur = kt & 1;
        if (kt + 1 < NK) load_tile(cur ^ 1, (kt + 1) * BK);

        #pragma unroll
        for (int k = 0; k < BK; k++) {
            const float4 a0 = *reinterpret_cast<const float4*>(&As[cur][k][ty * 8]);
            const float4 a1 = *reinterpret_cast<const float4*>(&As[cur][k][ty * 8 + 4]);
            const float4 b0 = *reinterpret_cast<const float4*>(&Bs[cur][k][tx * 8]);
            const float4 b1 = *reinterpret_cast<const float4*>(&Bs[cur][k][tx * 8 + 4]);

            u64 bp[4];
            bp[0] = pack2(b0.x, b0.y);
            bp[1] = pack2(b0.z, b0.w);
            bp[2] = pack2(b1.x, b1.y);
            bp[3] = pack2(b1.z, b1.w);

            const float av[8] = {a0.x, a0.y, a0.z, a0.w, a1.x, a1.y, a1.z, a1.w};
            #pragma unroll
            for (int i = 0; i < 8; i++) {
                const u64 ap = pack2_dup(av[i]);
                #pragma unroll
                for (int j = 0; j < 4; j++)
                    acc[i][j] = ffma2(ap, bp[j], acc[i][j]);
            }
        }
        __syncthreads();
    }

    // Epilogue: scale by 1/len and store
    const float* lb = lens + b * Ndim + m0;
    float* ob = out + (size_t)b * Ndim * Hdim + (size_t)m0 * Hdim + h0;

    #pragma unroll
    for (int i = 0; i < 8; i++) {
        const int row = ty * 8 + i;
        const float inv = 1.0f / lb[row];
        float r[8];
        #pragma unroll
        for (int j = 0; j < 4; j++) {
            float lo, hi;
            unpack2(acc[i][j], lo, hi);
            r[2 * j]     = lo * inv;
            r[2 * j + 1] = hi * inv;
        }
        float4* dst = reinterpret_cast<float4*>(ob + (size_t)row * Hdim + tx * 8);
        dst[0] = make_float4(r[0], r[1], r[2], r[3]);
        dst[1] = make_float4(r[4], r[5], r[6], r[7]);
    }
}

extern "C" void kernel_launch(void* const* d_in, const int* in_sizes, int n_in,
                              void* d_out, int out_size) {
    const float* doc  = (const float*)d_in[0];   // [8, 4096, 1024]
    const float* map  = (const float*)d_in[1];   // [8, 512, 4096]
    const float* lens = (const float*)d_in[2];   // [8, 512]
    float* out = (float*)d_out;                  // [8, 512, 1024]

    dim3 grid(Hdim / BN, Ndim / BM, Bdim);   // (8, 4, 8)
    dim3 block(NTHREADS);
    mean_pool_gemm<<<grid, block>>>(doc, map, lens, out);
}

// round 3
// speedup vs baseline: 2.9837x; 2.9837x over previous
#include <cuda_runtime.h>
#include <cstdint>

#define Bdim 8
#define Ndim 512
#define Sdim 4096
#define Hdim 1024

#define BM 128
#define BN 128
#define BK 16
#define STAGES 3
#define NKITER (Sdim / BK)          // 256
#define NTHREADS 256

#define A_ROW_F 20                   // 16 data + 4 pad floats
#define B_ROW_F 136                  // 128 data + 8 pad floats
#define A_STAGE_F (BM * A_ROW_F)     // 2560 floats (10240 B)
#define B_STAGE_F (BK * B_ROW_F)     // 2176 floats (8704 B)
#define STAGE_F   (A_STAGE_F + B_STAGE_F)   // 4736 floats (18944 B)
#define DYN_SMEM  (STAGES * STAGE_F * 4)    // 56832 B

__device__ __forceinline__ uint32_t smem_u32(const void* p) {
    uint32_t a;
    asm("{ .reg .u64 t; cvta.to.shared.u64 t, %1; cvt.u32.u64 %0, t; }" : "=r"(a) : "l"(p));
    return a;
}
__device__ __forceinline__ void cp16(uint32_t sdst, const void* gsrc) {
    asm volatile("cp.async.cg.shared.global [%0], [%1], 16;" :: "r"(sdst), "l"(gsrc));
}
__device__ __forceinline__ uint32_t tf32(float x) {
    uint32_t y;
    asm("cvt.rna.tf32.f32 %0, %1;" : "=r"(y) : "f"(x));
    return y;
}

__global__ void __launch_bounds__(NTHREADS, 2)
mean_pool_mma(const float* __restrict__ doc,   // [B,S,H]
              const float* __restrict__ map,   // [B,N,S]
              const float* __restrict__ lens,  // [B,N]
              float* __restrict__ out)         // [B,N,H]
{
    extern __shared__ float sm[];

    const int tid  = threadIdx.x;
    const int lane = tid & 31;
    const int w    = tid >> 5;
    const int wm   = w & 3;          // 4 warps along M (32 rows each)
    const int wn   = w >> 2;         // 2 warps along N (64 cols each)

    const int b  = blockIdx.z;
    const int m0 = blockIdx.y * BM;
    const int h0 = blockIdx.x * BN;

    const float* Ag = map + (size_t)b * Ndim * Sdim + (size_t)m0 * Sdim;  // [BM, S]
    const float* Bg = doc + (size_t)b * Sdim * Hdim + h0;                 // [S, BN]

    const uint32_t sbase = smem_u32(sm);

    // async tile loader: A -> [m][k] rows of 20 floats; B -> [k][n] rows of 136 floats
    auto load_stage = [&](int st, int k0) {
        const uint32_t abase = sbase + (uint32_t)(st * STAGE_F) * 4u;
        const uint32_t bbase = abase + (uint32_t)A_STAGE_F * 4u;
        #pragma unroll
        for (int i = 0; i < 2; i++) {          // A: 512 16B-chunks
            const int c = tid + NTHREADS * i;
            const int m = c >> 2, q = c & 3;
            cp16(abase + (uint32_t)(m * A_ROW_F + q * 4) * 4u,
                 Ag + (size_t)m * Sdim + k0 + q * 4);
        }
        #pragma unroll
        for (int i = 0; i < 2; i++) {          // B: 512 16B-chunks
            const int c = tid + NTHREADS * i;
            const int k = c >> 5, q = c & 31;
            cp16(bbase + (uint32_t)(k * B_ROW_F + q * 4) * 4u,
                 Bg + (size_t)(k0 + k) * Hdim + q * 4);
        }
    };

    float acc[2][8][4];
    #pragma unroll
    for (int i = 0; i < 2; i++)
        #pragma unroll
        for (int j = 0; j < 8; j++)
            #pragma unroll
            for (int r = 0; r < 4; r++)
                acc[i][j][r] = 0.0f;

    // prologue
    #pragma unroll
    for (int s = 0; s < STAGES - 1; s++) {
        load_stage(s, s * BK);
        asm volatile("cp.async.commit_group;");
    }

    // fragment base offsets (floats)
    const int a_off = (wm * 32 + (lane >> 2)) * A_ROW_F + (lane & 3);
    const int b_off = (lane & 3) * B_ROW_F + wn * 64 + (lane >> 2);

    #pragma unroll 1
    for (int kt = 0; kt < NKITER; kt++) {
        asm volatile("cp.async.wait_group 1;" ::: "memory");
        __syncthreads();

        const float* As = sm + (kt % STAGES) * STAGE_F;
        const float* Bs = As + A_STAGE_F;

        #pragma unroll
        for (int kk = 0; kk < 2; kk++) {       // two k=8 steps
            uint32_t a[2][4];
            #pragma unroll
            for (int i = 0; i < 2; i++) {
                const int base = a_off + i * 16 * A_ROW_F + kk * 8;
                a[i][0] = tf32(As[base]);
                a[i][1] = tf32(As[base + 8 * A_ROW_F]);
                a[i][2] = tf32(As[base + 4]);
                a[i][3] = tf32(As[base + 8 * A_ROW_F + 4]);
            }
            uint32_t bfr[8][2];
            #pragma unroll
            for (int j = 0; j < 8; j++) {
                const int bb = b_off + kk * 8 * B_ROW_F + j * 8;
                bfr[j][0] = tf32(Bs[bb]);
                bfr[j][1] = tf32(Bs[bb + 4 * B_ROW_F]);
            }
            #pragma unroll
            for (int i = 0; i < 2; i++)
                #pragma unroll
                for (int j = 0; j < 8; j++) {
                    asm volatile(
                        "mma.sync.aligned.m16n8k8.row.col.f32.tf32.tf32.f32 "
                        "{%0,%1,%2,%3}, {%4,%5,%6,%7}, {%8,%9}, {%0,%1,%2,%3};"
                        : "+f"(acc[i][j][0]), "+f"(acc[i][j][1]),
                          "+f"(acc[i][j][2]), "+f"(acc[i][j][3])
                        : "r"(a[i][0]), "r"(a[i][1]), "r"(a[i][2]), "r"(a[i][3]),
                          "r"(bfr[j][0]), "r"(bfr[j][1]));
                }
        }

        const int ls = kt + STAGES - 1;
        if (ls < NKITER) load_stage(ls % STAGES, ls * BK);
        asm volatile("cp.async.commit_group;");
    }

    // epilogue: scale by 1/len, store float2 pairs
    const float* lb = lens + b * Ndim;
    #pragma unroll
    for (int i = 0; i < 2; i++) {
        const int r0 = m0 + wm * 32 + i * 16 + (lane >> 2);
        const int r1 = r0 + 8;
        const float inv0 = 1.0f / lb[r0];
        const float inv1 = 1.0f / lb[r1];
        float* o0 = out + (size_t)b * Ndim * Hdim + (size_t)r0 * Hdim + h0;
        float* o1 = out + (size_t)b * Ndim * Hdim + (size_t)r1 * Hdim + h0;
        #pragma unroll
        for (int j = 0; j < 8; j++) {
            const int h = wn * 64 + j * 8 + 2 * (lane & 3);
            *reinterpret_cast<float2*>(o0 + h) =
                make_float2(acc[i][j][0] * inv0, acc[i][j][1] * inv0);
            *reinterpret_cast<float2*>(o1 + h) =
                make_float2(acc[i][j][2] * inv1, acc[i][j][3] * inv1);
        }
    }
}

extern "C" void kernel_launch(void* const* d_in, const int* in_sizes, int n_in,
                              void* d_out, int out_size) {
    const float* doc  = (const float*)d_in[0];   // [8, 4096, 1024]
    const float* map  = (const float*)d_in[1];   // [8, 512, 4096]
    const float* lens = (const float*)d_in[2];   // [8, 512]
    float* out = (float*)d_out;                  // [8, 512, 1024]

    cudaFuncSetAttribute(mean_pool_mma, cudaFuncAttributeMaxDynamicSharedMemorySize, DYN_SMEM);

    dim3 grid(Hdim / BN, Ndim / BM, Bdim);   // (8, 4, 8) = 256 CTAs
    mean_pool_mma<<<grid, NTHREADS, DYN_SMEM>>>(doc, map, lens, out);
}

// round 4
// speedup vs baseline: 3.0958x; 1.0376x over previous
#include <cuda_runtime.h>
#include <cstdint>

#define Bdim 8
#define Ndim 512
#define Sdim 4096
#define Hdim 1024

#define BM 128
#define BN 128
#define BK 16
#define STAGES 4
#define NKITER (Sdim / BK)          // 256
#define NTHREADS 128

#define A_ROW_F 20                   // 16 data + 4 pad floats
#define B_ROW_F 136                  // 128 data + 8 pad floats
#define A_STAGE_F (BM * A_ROW_F)     // 2560 floats
#define B_STAGE_F (BK * B_ROW_F)     // 2176 floats
#define STAGE_F   (A_STAGE_F + B_STAGE_F)   // 4736 floats (18944 B)
#define DYN_SMEM  (STAGES * STAGE_F * 4)    // 75776 B

__device__ __forceinline__ uint32_t smem_u32(const void* p) {
    uint32_t a;
    asm("{ .reg .u64 t; cvta.to.shared.u64 t, %1; cvt.u32.u64 %0, t; }" : "=r"(a) : "l"(p));
    return a;
}
__device__ __forceinline__ void cp16(uint32_t sdst, const void* gsrc) {
    asm volatile("cp.async.cg.shared.global [%0], [%1], 16;" :: "r"(sdst), "l"(gsrc));
}
__device__ __forceinline__ uint32_t tf32(float x) {
    uint32_t y;
    asm("cvt.rna.tf32.f32 %0, %1;" : "=r"(y) : "f"(x));
    return y;
}

__global__ void __launch_bounds__(NTHREADS, 2)
mean_pool_mma(const float* __restrict__ doc,   // [B,S,H]
              const float* __restrict__ map,   // [B,N,S]
              const float* __restrict__ lens,  // [B,N]
              float* __restrict__ out)         // [B,N,H]
{
    extern __shared__ float sm[];

    const int tid  = threadIdx.x;
    const int lane = tid & 31;
    const int w    = tid >> 5;       // 4 warps
    const int wm   = w & 1;          // 2 warps along M (64 rows each)
    const int wn   = w >> 1;         // 2 warps along N (64 cols each)

    const int b  = blockIdx.z;
    const int m0 = blockIdx.y * BM;
    const int h0 = blockIdx.x * BN;

    const float* Ag = map + (size_t)b * Ndim * Sdim + (size_t)m0 * Sdim;  // [BM, S]
    const float* Bg = doc + (size_t)b * Sdim * Hdim + h0;                 // [S, BN]

    const uint32_t sbase = smem_u32(sm);

    // async tile loader: A -> [m][k] rows of 20 floats; B -> [k][n] rows of 136 floats
    auto load_stage = [&](int st, int k0) {
        const uint32_t abase = sbase + (uint32_t)(st * STAGE_F) * 4u;
        const uint32_t bbase = abase + (uint32_t)A_STAGE_F * 4u;
        #pragma unroll
        for (int i = 0; i < 4; i++) {          // A: 512 16B-chunks
            const int c = tid + NTHREADS * i;
            const int m = c >> 2, q = c & 3;
            cp16(abase + (uint32_t)(m * A_ROW_F + q * 4) * 4u,
                 Ag + (size_t)m * Sdim + k0 + q * 4);
        }
        #pragma unroll
        for (int i = 0; i < 4; i++) {          // B: 512 16B-chunks
            const int c = tid + NTHREADS * i;
            const int k = c >> 5, q = c & 31;
            cp16(bbase + (uint32_t)(k * B_ROW_F + q * 4) * 4u,
                 Bg + (size_t)(k0 + k) * Hdim + q * 4);
        }
    };

    float acc[4][8][4];
    #pragma unroll
    for (int i = 0; i < 4; i++)
        #pragma unroll
        for (int j = 0; j < 8; j++)
            #pragma unroll
            for (int r = 0; r < 4; r++)
                acc[i][j][r] = 0.0f;

    // prologue: stages 0..STAGES-2
    #pragma unroll
    for (int s = 0; s < STAGES - 1; s++) {
        load_stage(s, s * BK);
        asm volatile("cp.async.commit_group;");
    }

    // fragment base offsets (floats)
    const int a_off = (wm * 64 + (lane >> 2)) * A_ROW_F + (lane & 3);
    const int b_off = (lane & 3) * B_ROW_F + wn * 64 + (lane >> 2);

    #pragma unroll 1
    for (int kt = 0; kt < NKITER; kt++) {
        asm volatile("cp.async.wait_group 2;" ::: "memory");
        __syncthreads();

        const float* As = sm + (kt % STAGES) * STAGE_F;
        const float* Bs = As + A_STAGE_F;

        #pragma unroll
        for (int kk = 0; kk < 2; kk++) {       // two k=8 steps
            uint32_t a[4][4];
            #pragma unroll
            for (int i = 0; i < 4; i++) {
                const int base = a_off + i * 16 * A_ROW_F + kk * 8;
                a[i][0] = tf32(As[base]);
                a[i][1] = tf32(As[base + 8 * A_ROW_F]);
                a[i][2] = tf32(As[base + 4]);
                a[i][3] = tf32(As[base + 8 * A_ROW_F + 4]);
            }
            uint32_t bfr[8][2];
            #pragma unroll
            for (int j = 0; j < 8; j++) {
                const int bb = b_off + kk * 8 * B_ROW_F + j * 8;
                bfr[j][0] = tf32(Bs[bb]);
                bfr[j][1] = tf32(Bs[bb + 4 * B_ROW_F]);
            }
            #pragma unroll
            for (int i = 0; i < 4; i++)
                #pragma unroll
                for (int j = 0; j < 8; j++) {
                    asm volatile(
                        "mma.sync.aligned.m16n8k8.row.col.f32.tf32.tf32.f32 "
                        "{%0,%1,%2,%3}, {%4,%5,%6,%7}, {%8,%9}, {%0,%1,%2,%3};"
                        : "+f"(acc[i][j][0]), "+f"(acc[i][j][1]),
                          "+f"(acc[i][j][2]), "+f"(acc[i][j][3])
                        : "r"(a[i][0]), "r"(a[i][1]), "r"(a[i][2]), "r"(a[i][3]),
                          "r"(bfr[j][0]), "r"(bfr[j][1]));
                }
        }

        const int ls = kt + STAGES - 1;
        if (ls < NKITER) load_stage(ls % STAGES, ls * BK);
        asm volatile("cp.async.commit_group;");
    }

    // epilogue: scale by 1/len, store float2 pairs
    const float* lb = lens + b * Ndim;
    #pragma unroll
    for (int i = 0; i < 4; i++) {
        const int r0 = m0 + wm * 64 + i * 16 + (lane >> 2);
        const int r1 = r0 + 8;
        const float inv0 = 1.0f / lb[r0];
        const float inv1 = 1.0f / lb[r1];
        float* o0 = out + (size_t)b * Ndim * Hdim + (size_t)r0 * Hdim + h0;
        float* o1 = out + (size_t)b * Ndim * Hdim + (size_t)r1 * Hdim + h0;
        #pragma unroll
        for (int j = 0; j < 8; j++) {
            const int h = wn * 64 + j * 8 + 2 * (lane & 3);
            *reinterpret_cast<float2*>(o0 + h) =
                make_float2(acc[i][j][0] * inv0, acc[i][j][1] * inv0);
            *reinterpret_cast<float2*>(o1 + h) =
                make_float2(acc[i][j][2] * inv1, acc[i][j][3] * inv1);
        }
    }
}

extern "C" void kernel_launch(void* const* d_in, const int* in_sizes, int n_in,
                              void* d_out, int out_size) {
    const float* doc  = (const float*)d_in[0];   // [8, 4096, 1024]
    const float* map  = (const float*)d_in[1];   // [8, 512, 4096]
    const float* lens = (const float*)d_in[2];   // [8, 512]
    float* out = (float*)d_out;                  // [8, 512, 1024]

    cudaFuncSetAttribute(mean_pool_mma, cudaFuncAttributeMaxDynamicSharedMemorySize, DYN_SMEM);

    dim3 grid(Hdim / BN, Ndim / BM, Bdim);   // (8, 4, 8) = 256 CTAs
    mean_pool_mma<<<grid, NTHREADS, DYN_SMEM>>>(doc, map, lens, out);
}

// round 5
// speedup vs baseline: 4.7419x; 1.5317x over previous
#include <cuda_runtime.h>
#include <cuda_fp16.h>
#include <cstdint>

#define Bdim 8
#define Ndim 512
#define Sdim 4096
#define Hdim 1024

#define BM 128
#define BN 128
#define BK 32
#define STAGES 3
#define NKITER (Sdim / BK)          // 128
#define NTHREADS 128

#define A_ROW_F 36                   // 32 data + 4 pad floats
#define B_ROW_F 132                  // 128 data + 4 pad floats
#define A_STAGE_F (BM * A_ROW_F)     // 4608 floats
#define B_STAGE_F (BK * B_ROW_F)     // 4224 floats
#define STAGE_F   (A_STAGE_F + B_STAGE_F)   // 8832 floats (35328 B)
#define DYN_SMEM  (STAGES * STAGE_F * 4)    // 105984 B

__device__ __forceinline__ uint32_t smem_u32(const void* p) {
    uint32_t a;
    asm("{ .reg .u64 t; cvta.to.shared.u64 t, %1; cvt.u32.u64 %0, t; }" : "=r"(a) : "l"(p));
    return a;
}
__device__ __forceinline__ void cp16(uint32_t sdst, const void* gsrc) {
    asm volatile("cp.async.cg.shared.global [%0], [%1], 16;" :: "r"(sdst), "l"(gsrc));
}
// pack two f32 -> f16x2 reg (lo = first element, hi = second)
__device__ __forceinline__ uint32_t packh2(float lo, float hi) {
    __half2 h = __floats2half2_rn(lo, hi);
    return *reinterpret_cast<uint32_t*>(&h);
}

__global__ void __launch_bounds__(NTHREADS, 2)
mean_pool_mma(const float* __restrict__ doc,   // [B,S,H]
              const float* __restrict__ map,   // [B,N,S]
              const float* __restrict__ lens,  // [B,N]
              float* __restrict__ out)         // [B,N,H]
{
    extern __shared__ float sm[];

    const int tid  = threadIdx.x;
    const int lane = tid & 31;
    const int w    = tid >> 5;       // 4 warps
    const int wm   = w & 1;          // 2 warps along M (64 rows each)
    const int wn   = w >> 1;         // 2 warps along N (64 cols each)
    const int gid  = lane >> 2;      // 0..7
    const int tq   = lane & 3;       // 0..3

    const int b  = blockIdx.z;
    const int m0 = blockIdx.y * BM;
    const int h0 = blockIdx.x * BN;

    const float* Ag = map + (size_t)b * Ndim * Sdim + (size_t)m0 * Sdim;  // [BM, S]
    const float* Bg = doc + (size_t)b * Sdim * Hdim + h0;                 // [S, BN]

    const uint32_t sbase = smem_u32(sm);

    // async tile loader (fp32): A -> [m][k] rows of 36 floats; B -> [k][n] rows of 132 floats
    auto load_stage = [&](int st, int k0) {
        const uint32_t abase = sbase + (uint32_t)(st * STAGE_F) * 4u;
        const uint32_t bbase = abase + (uint32_t)A_STAGE_F * 4u;
        #pragma unroll
        for (int i = 0; i < 8; i++) {          // A: 1024 16B-chunks
            const int c = tid + NTHREADS * i;
            const int m = c >> 3, q = c & 7;
            cp16(abase + (uint32_t)(m * A_ROW_F + q * 4) * 4u,
                 Ag + (size_t)m * Sdim + k0 + q * 4);
        }
        #pragma unroll
        for (int i = 0; i < 8; i++) {          // B: 1024 16B-chunks
            const int c = tid + NTHREADS * i;
            const int k = c >> 5, q = c & 31;
            cp16(bbase + (uint32_t)(k * B_ROW_F + q * 4) * 4u,
                 Bg + (size_t)(k0 + k) * Hdim + q * 4);
        }
    };

    float acc[4][8][4];
    #pragma unroll
    for (int i = 0; i < 4; i++)
        #pragma unroll
        for (int j = 0; j < 8; j++)
            #pragma unroll
            for (int r = 0; r < 4; r++)
                acc[i][j][r] = 0.0f;

    // prologue: stages 0..STAGES-2
    #pragma unroll
    for (int s = 0; s < STAGES - 1; s++) {
        load_stage(s, s * BK);
        asm volatile("cp.async.commit_group;");
    }

    #pragma unroll 1
    for (int kt = 0; kt < NKITER; kt++) {
        asm volatile("cp.async.wait_group 1;" ::: "memory");
        __syncthreads();

        const float* As = sm + (kt % STAGES) * STAGE_F;
        const float* Bs = As + A_STAGE_F;

        #pragma unroll
        for (int kc = 0; kc < 2; kc++) {       // two k=16 steps
            // A fragments: 4 m-tiles x {a0,a1,a2,a3}, f16x2 each
            uint32_t a[4][4];
            #pragma unroll
            for (int i = 0; i < 4; i++) {
                const int r = wm * 64 + i * 16 + gid;
                const int cbase = kc * 16 + tq * 2;
                const float2 v0 = *reinterpret_cast<const float2*>(&As[r * A_ROW_F + cbase]);
                const float2 v1 = *reinterpret_cast<const float2*>(&As[(r + 8) * A_ROW_F + cbase]);
                const float2 v2 = *reinterpret_cast<const float2*>(&As[r * A_ROW_F + cbase + 8]);
                const float2 v3 = *reinterpret_cast<const float2*>(&As[(r + 8) * A_ROW_F + cbase + 8]);
                a[i][0] = packh2(v0.x, v0.y);
                a[i][1] = packh2(v1.x, v1.y);
                a[i][2] = packh2(v2.x, v2.y);
                a[i][3] = packh2(v3.x, v3.y);
            }
            // B fragments: 8 n-tiles x {b0,b1}
            uint32_t bfr[8][2];
            #pragma unroll
            for (int j = 0; j < 8; j++) {
                const int n = wn * 64 + j * 8 + gid;
                const int k0r = kc * 16 + tq * 2;
                bfr[j][0] = packh2(Bs[k0r * B_ROW_F + n],       Bs[(k0r + 1) * B_ROW_F + n]);
                bfr[j][1] = packh2(Bs[(k0r + 8) * B_ROW_F + n], Bs[(k0r + 9) * B_ROW_F + n]);
            }
            #pragma unroll
            for (int i = 0; i < 4; i++)
                #pragma unroll
                for (int j = 0; j < 8; j++) {
                    asm volatile(
                        "mma.sync.aligned.m16n8k16.row.col.f32.f16.f16.f32 "
                        "{%0,%1,%2,%3}, {%4,%5,%6,%7}, {%8,%9}, {%0,%1,%2,%3};"
                        : "+f"(acc[i][j][0]), "+f"(acc[i][j][1]),
                          "+f"(acc[i][j][2]), "+f"(acc[i][j][3])
                        : "r"(a[i][0]), "r"(a[i][1]), "r"(a[i][2]), "r"(a[i][3]),
                          "r"(bfr[j][0]), "r"(bfr[j][1]));
                }
        }

        const int ls = kt + STAGES - 1;
        if (ls < NKITER) load_stage(ls % STAGES, ls * BK);
        asm volatile("cp.async.commit_group;");
    }

    // epilogue: scale by 1/len, store float2 pairs
    const float* lb = lens + b * Ndim;
    #pragma unroll
    for (int i = 0; i < 4; i++) {
        const int r0 = m0 + wm * 64 + i * 16 + gid;
        const int r1 = r0 + 8;
        const float inv0 = 1.0f / lb[r0];
        const float inv1 = 1.0f / lb[r1];
        float* o0 = out + (size_t)b * Ndim * Hdim + (size_t)r0 * Hdim + h0;
        float* o1 = out + (size_t)b * Ndim * Hdim + (size_t)r1 * Hdim + h0;
        #pragma unroll
        for (int j = 0; j < 8; j++) {
            const int h = wn * 64 + j * 8 + 2 * tq;
            *reinterpret_cast<float2*>(o0 + h) =
                make_float2(acc[i][j][0] * inv0, acc[i][j][1] * inv0);
            *reinterpret_cast<float2*>(o1 + h) =
                make_float2(acc[i][j][2] * inv1, acc[i][j][3] * inv1);
        }
    }
}

extern "C" void kernel_launch(void* const* d_in, const int* in_sizes, int n_in,
                              void* d_out, int out_size) {
    const float* doc  = (const float*)d_in[0];   // [8, 4096, 1024]
    const float* map  = (const float*)d_in[1];   // [8, 512, 4096]
    const float* lens = (const float*)d_in[2];   // [8, 512]
    float* out = (float*)d_out;                  // [8, 512, 1024]

    cudaFuncSetAttribute(mean_pool_mma, cudaFuncAttributeMaxDynamicSharedMemorySize, DYN_SMEM);

    dim3 grid(Hdim / BN, Ndim / BM, Bdim);   // (8, 4, 8) = 256 CTAs
    mean_pool_mma<<<grid, NTHREADS, DYN_SMEM>>>(doc, map, lens, out);
}

// round 6
// speedup vs baseline: 5.5000x; 1.1599x over previous
#include <cuda_runtime.h>
#include <cuda_fp16.h>
#include <cstdint>

#define Bdim 8
#define Ndim 512
#define Sdim 4096
#define Hdim 1024

#define BM 128
#define BN 128
#define BK 64
#define STAGES 3
#define NKITER (Sdim / BK)          // 64
#define NTHREADS 256

// fp16 SMEM tiles with padded rows (conflict-free ldmatrix groups)
#define A_ROW_B 144                  // 64 halves data (128B) + 16B pad
#define B_ROW_B 272                  // 128 halves data (256B) + 16B pad
#define A_STAGE_B (BM * A_ROW_B)     // 18432 B
#define B_STAGE_B (BK * B_ROW_B)     // 17408 B
#define STAGE_B   (A_STAGE_B + B_STAGE_B)   // 35840 B
#define DYN_SMEM  (STAGES * STAGE_B)        // 107520 B

// fp16 scratch (static device globals -- allowed scratch path)
__device__ __align__(16) __half g_doc_h[(size_t)Bdim * Sdim * Hdim];  // 67.1 MB
__device__ __align__(16) __half g_map_h[(size_t)Bdim * Ndim * Sdim];  // 33.6 MB

__device__ __forceinline__ uint32_t smem_u32(const void* p) {
    uint32_t a;
    asm("{ .reg .u64 t; cvta.to.shared.u64 t, %1; cvt.u32.u64 %0, t; }" : "=r"(a) : "l"(p));
    return a;
}
__device__ __forceinline__ void cp16(uint32_t sdst, const void* gsrc) {
    asm volatile("cp.async.cg.shared.global [%0], [%1], 16;" :: "r"(sdst), "l"(gsrc));
}
__device__ __forceinline__ uint32_t h2u(__half2 h) {
    return *reinterpret_cast<uint32_t*>(&h);
}

// ---------------- conversion pre-pass ----------------
__device__ __forceinline__ void cvt_body(const float* __restrict__ src,
                                         __half* __restrict__ dst, size_t n8) {
    size_t i = (size_t)blockIdx.x * blockDim.x + threadIdx.x;
    const size_t stride = (size_t)gridDim.x * blockDim.x;
    const float4* s4 = reinterpret_cast<const float4*>(src);
    uint4* d4 = reinterpret_cast<uint4*>(dst);
    for (; i < n8; i += stride) {
        const float4 v0 = s4[2 * i];
        const float4 v1 = s4[2 * i + 1];
        uint4 o;
        o.x = h2u(__floats2half2_rn(v0.x, v0.y));
        o.y = h2u(__floats2half2_rn(v0.z, v0.w));
        o.z = h2u(__floats2half2_rn(v1.x, v1.y));
        o.w = h2u(__floats2half2_rn(v1.z, v1.w));
        d4[i] = o;
    }
}
__global__ void __launch_bounds__(256) cvt_doc(const float* __restrict__ src) {
    cvt_body(src, g_doc_h, (size_t)Bdim * Sdim * Hdim / 8);
}
__global__ void __launch_bounds__(256) cvt_map(const float* __restrict__ src) {
    cvt_body(src, g_map_h, (size_t)Bdim * Ndim * Sdim / 8);
}

// ---------------- main GEMM ----------------
__global__ void __launch_bounds__(NTHREADS, 2)
mean_pool_mma(const float* __restrict__ lens,  // [B,N]
              float* __restrict__ out)         // [B,N,H]
{
    extern __shared__ char smraw[];

    const int tid  = threadIdx.x;
    const int lane = tid & 31;
    const int w    = tid >> 5;       // 8 warps
    const int wm   = w & 3;          // 4 warps along M (32 rows each)
    const int wn   = w >> 2;         // 2 warps along N (64 cols each)

    const int b  = blockIdx.z;
    const int m0 = blockIdx.y * BM;
    const int h0 = blockIdx.x * BN;

    const __half* Ag = g_map_h + (size_t)b * Ndim * Sdim + (size_t)m0 * Sdim;  // [BM, S]
    const __half* Bg = g_doc_h + (size_t)b * Sdim * Hdim + h0;                 // [S, BN]

    const uint32_t sbase = smem_u32(smraw);

    // async tile loader: A 128x64 halves (rows 144B), B 64x128 halves (rows 272B)
    auto load_stage = [&](int st, int k0) {
        const uint32_t abase = sbase + (uint32_t)(st * STAGE_B);
        const uint32_t bbase = abase + A_STAGE_B;
        #pragma unroll
        for (int i = 0; i < 4; i++) {          // A: 1024 16B-chunks
            const int c = tid + NTHREADS * i;
            const int m = c >> 3, q = c & 7;
            cp16(abase + (uint32_t)(m * A_ROW_B + q * 16),
                 Ag + (size_t)m * Sdim + k0 + q * 8);
        }
        #pragma unroll
        for (int i = 0; i < 4; i++) {          // B: 1024 16B-chunks
            const int c = tid + NTHREADS * i;
            const int k = c >> 4, q = c & 15;
            cp16(bbase + (uint32_t)(k * B_ROW_B + q * 16),
                 Bg + (size_t)(k0 + k) * Hdim + q * 8);
        }
    };

    float acc[2][8][4];
    #pragma unroll
    for (int i = 0; i < 2; i++)
        #pragma unroll
        for (int j = 0; j < 8; j++)
            #pragma unroll
            for (int r = 0; r < 4; r++)
                acc[i][j][r] = 0.0f;

    // prologue
    #pragma unroll
    for (int s = 0; s < STAGES - 1; s++) {
        load_stage(s, s * BK);
        asm volatile("cp.async.commit_group;");
    }

    // ldmatrix lane address components
    const int t8 = lane >> 3;        // 0..3 tile index within x4
    const int r8 = lane & 7;         // row within 8x8 tile
    // A: tile t -> row (t&1)*8 + r8 (within m16), col (t>>1)*8 halves
    const uint32_t a_lane_off =
        (uint32_t)(((t8 & 1) * 8 + r8) * A_ROW_B + (t8 >> 1) * 16);
    // B: tile t -> k-row (t&1)*8 + r8 (within k16), n-col (t>>1)*8 halves
    const uint32_t b_lane_off =
        (uint32_t)(((t8 & 1) * 8 + r8) * B_ROW_B + (t8 >> 1) * 16);

    #pragma unroll 1
    for (int kt = 0; kt < NKITER; kt++) {
        asm volatile("cp.async.wait_group 1;" ::: "memory");
        __syncthreads();

        const int st = kt % STAGES;
        const uint32_t abase = sbase + (uint32_t)(st * STAGE_B);
        const uint32_t bbase = abase + A_STAGE_B;
        // warp bases
        const uint32_t awarp = abase + (uint32_t)((wm * 32) * A_ROW_B) + a_lane_off;
        const uint32_t bwarp = bbase + (uint32_t)((wn * 64) * 2) + b_lane_off;

        #pragma unroll
        for (int kc = 0; kc < 4; kc++) {       // four k=16 steps
            // A fragments: 2 m16 tiles
            uint32_t a[2][4];
            #pragma unroll
            for (int i = 0; i < 2; i++) {
                const uint32_t addr = awarp + (uint32_t)(i * 16 * A_ROW_B + kc * 32);
                asm volatile(
                    "ldmatrix.sync.aligned.m8n8.x4.shared.b16 {%0,%1,%2,%3}, [%4];"
                    : "=r"(a[i][0]), "=r"(a[i][1]), "=r"(a[i][2]), "=r"(a[i][3])
                    : "r"(addr));
            }
            // B fragments: 8 n8 tiles via 4 x4.trans (each covers n16 x k16)
            uint32_t bfr[8][2];
            #pragma unroll
            for (int jt = 0; jt < 4; jt++) {
                const uint32_t addr = bwarp + (uint32_t)(kc * 16 * B_ROW_B + jt * 32);
                asm volatile(
                    "ldmatrix.sync.aligned.m8n8.x4.trans.shared.b16 {%0,%1,%2,%3}, [%4];"
                    : "=r"(bfr[2 * jt][0]), "=r"(bfr[2 * jt][1]),
                      "=r"(bfr[2 * jt + 1][0]), "=r"(bfr[2 * jt + 1][1])
                    : "r"(addr));
            }
            #pragma unroll
            for (int i = 0; i < 2; i++)
                #pragma unroll
                for (int j = 0; j < 8; j++) {
                    asm volatile(
                        "mma.sync.aligned.m16n8k16.row.col.f32.f16.f16.f32 "
                        "{%0,%1,%2,%3}, {%4,%5,%6,%7}, {%8,%9}, {%0,%1,%2,%3};"
                        : "+f"(acc[i][j][0]), "+f"(acc[i][j][1]),
                          "+f"(acc[i][j][2]), "+f"(acc[i][j][3])
                        : "r"(a[i][0]), "r"(a[i][1]), "r"(a[i][2]), "r"(a[i][3]),
                          "r"(bfr[j][0]), "r"(bfr[j][1]));
                }
        }

        const int ls = kt + STAGES - 1;
        if (ls < NKITER) load_stage(ls % STAGES, ls * BK);
        asm volatile("cp.async.commit_group;");
    }

    // epilogue: scale by 1/len, store float2 pairs
    const float* lb = lens + b * Ndim;
    const int gid = lane >> 2, tq = lane & 3;
    #pragma unroll
    for (int i = 0; i < 2; i++) {
        const int r0 = m0 + wm * 32 + i * 16 + gid;
        const int r1 = r0 + 8;
        const float inv0 = 1.0f / lb[r0];
        const float inv1 = 1.0f / lb[r1];
        float* o0 = out + (size_t)b * Ndim * Hdim + (size_t)r0 * Hdim + h0;
        float* o1 = out + (size_t)b * Ndim * Hdim + (size_t)r1 * Hdim + h0;
        #pragma unroll
        for (int j = 0; j < 8; j++) {
            const int h = wn * 64 + j * 8 + 2 * tq;
            *reinterpret_cast<float2*>(o0 + h) =
                make_float2(acc[i][j][0] * inv0, acc[i][j][1] * inv0);
            *reinterpret_cast<float2*>(o1 + h) =
                make_float2(acc[i][j][2] * inv1, acc[i][j][3] * inv1);
        }
    }
}

extern "C" void kernel_launch(void* const* d_in, const int* in_sizes, int n_in,
                              void* d_out, int out_size) {
    const float* doc  = (const float*)d_in[0];   // [8, 4096, 1024]
    const float* map  = (const float*)d_in[1];   // [8, 512, 4096]
    const float* lens = (const float*)d_in[2];   // [8, 512]
    float* out = (float*)d_out;                  // [8, 512, 1024]

    cvt_doc<<<2048, 256>>>(doc);
    cvt_map<<<1024, 256>>>(map);

    cudaFuncSetAttribute(mean_pool_mma, cudaFuncAttributeMaxDynamicSharedMemorySize, DYN_SMEM);
    dim3 grid(Hdim / BN, Ndim / BM, Bdim);   // (8, 4, 8) = 256 CTAs
    mean_pool_mma<<<grid, NTHREADS, DYN_SMEM>>>(lens, out);
}